// round 3
// baseline (speedup 1.0000x reference)
#include <cuda_runtime.h>
#include <cuda_bf16.h>

#define BB 32
#define DD 640
#define MM 1024
#define TRI (DD*(DD+1)/2)          /* 205120 */
#define TEMPR (1.0f/(2.0f*DD*MM))  /* 1/1310720 */
#define EPSV 1e-5f
#define NT (DD/64)                  /* 10 tiles per dim */

// Scratch (device globals; no runtime allocation).
__device__ float g_dcov[(size_t)BB*DD*DD];   // 52.4 MB
__device__ float g_diag[BB*DD];
__device__ float g_rowsum[BB*DD];
__device__ float g_tot[BB];

// ---------------------------------------------------------------------------
// Kernel 1: diag[b,i] = sum_m x[b,i,m]^2   (one warp per row)
// ---------------------------------------------------------------------------
__global__ void diag_kernel(const float* __restrict__ x) {
    int w = (blockIdx.x * blockDim.x + threadIdx.x) >> 5;
    int lane = threadIdx.x & 31;
    if (w >= BB * DD) return;
    const float4* row = reinterpret_cast<const float4*>(x + (size_t)w * MM);
    float s = 0.f;
    #pragma unroll
    for (int m = lane; m < MM / 4; m += 32) {
        float4 v = row[m];
        s += v.x * v.x + v.y * v.y + v.z * v.z + v.w * v.w;
    }
    #pragma unroll
    for (int o = 16; o > 0; o >>= 1) s += __shfl_down_sync(0xffffffffu, s, o);
    if (lane == 0) g_diag[w] = s;
}

// ---------------------------------------------------------------------------
// Kernel 2: symmetric tiled SGEMM (64x64 tile, K-chunk 16) with fused
// dcov epilogue: dcov = sqrt(temp*max(diag_i+diag_j-2*G,0)+eps).
// Only upper-triangular tiles computed; result mirrored.
// ---------------------------------------------------------------------------
__global__ __launch_bounds__(256) void gram_kernel(const float* __restrict__ x) {
    // Map linear tile id -> (ti, tj) with ti <= tj (55 tiles).
    int lin = blockIdx.x;
    int bb  = blockIdx.y;
    int ti = 0, rem = lin;
    while (rem >= NT - ti) { rem -= NT - ti; ti++; }
    int tj = ti + rem;

    __shared__ float As[16][64];
    __shared__ float Bs[16][64];

    const float* xb = x + (size_t)bb * DD * MM;
    const float* Ap = xb + (size_t)(ti * 64) * MM;
    const float* Bp = xb + (size_t)(tj * 64) * MM;

    int t  = threadIdx.x;
    int lr = t >> 2;        // row within tile for loading (0..63)
    int lq = t & 3;         // which float4 of the 16-wide K chunk
    int tx = t & 15;        // j micro-tile
    int ty = t >> 4;        // i micro-tile

    float c[4][4];
    #pragma unroll
    for (int i = 0; i < 4; i++)
        #pragma unroll
        for (int j = 0; j < 4; j++) c[i][j] = 0.f;

    const float* Aload = Ap + (size_t)lr * MM + lq * 4;
    const float* Bload = Bp + (size_t)lr * MM + lq * 4;

    for (int k0 = 0; k0 < MM; k0 += 16) {
        float4 a = *reinterpret_cast<const float4*>(Aload + k0);
        float4 b = *reinterpret_cast<const float4*>(Bload + k0);
        __syncthreads();
        As[lq * 4 + 0][lr] = a.x; As[lq * 4 + 1][lr] = a.y;
        As[lq * 4 + 2][lr] = a.z; As[lq * 4 + 3][lr] = a.w;
        Bs[lq * 4 + 0][lr] = b.x; Bs[lq * 4 + 1][lr] = b.y;
        Bs[lq * 4 + 2][lr] = b.z; Bs[lq * 4 + 3][lr] = b.w;
        __syncthreads();
        #pragma unroll
        for (int kk = 0; kk < 16; kk++) {
            float4 av = *reinterpret_cast<const float4*>(&As[kk][ty * 4]);
            float4 bv = *reinterpret_cast<const float4*>(&Bs[kk][tx * 4]);
            float ar[4] = {av.x, av.y, av.z, av.w};
            float br[4] = {bv.x, bv.y, bv.z, bv.w};
            #pragma unroll
            for (int i = 0; i < 4; i++)
                #pragma unroll
                for (int j = 0; j < 4; j++)
                    c[i][j] += ar[i] * br[j];
        }
    }

    // Epilogue: dcov transform + symmetric store
    int gi0 = ti * 64 + ty * 4;
    int gj0 = tj * 64 + tx * 4;
    float di[4], dj[4];
    #pragma unroll
    for (int i = 0; i < 4; i++) di[i] = __ldg(&g_diag[bb * DD + gi0 + i]);
    #pragma unroll
    for (int j = 0; j < 4; j++) dj[j] = __ldg(&g_diag[bb * DD + gj0 + j]);

    float* dc = g_dcov + (size_t)bb * DD * DD;
    #pragma unroll
    for (int i = 0; i < 4; i++) {
        #pragma unroll
        for (int j = 0; j < 4; j++) {
            float v = di[i] + dj[j] - 2.f * c[i][j];
            v = fmaxf(v, 0.f);
            v = sqrtf(TEMPR * v + EPSV);
            dc[(size_t)(gi0 + i) * DD + (gj0 + j)] = v;
            dc[(size_t)(gj0 + j) * DD + (gi0 + i)] = v;
        }
    }
}

// ---------------------------------------------------------------------------
// Kernel 3: row sums of dcov (symmetric -> row sums == col sums)
// ---------------------------------------------------------------------------
__global__ void rowsum_kernel() {
    int w = (blockIdx.x * blockDim.x + threadIdx.x) >> 5;
    int lane = threadIdx.x & 31;
    if (w >= BB * DD) return;
    const float4* row = reinterpret_cast<const float4*>(g_dcov + (size_t)w * DD);
    float s = 0.f;
    #pragma unroll
    for (int j = lane; j < DD / 4; j += 32) {
        float4 v = row[j];
        s += v.x + v.y + v.z + v.w;
    }
    #pragma unroll
    for (int o = 16; o > 0; o >>= 1) s += __shfl_down_sync(0xffffffffu, s, o);
    if (lane == 0) g_rowsum[w] = s;
}

// ---------------------------------------------------------------------------
// Kernel 4: per-batch total (deterministic block reduce, no float atomics)
// ---------------------------------------------------------------------------
__global__ void tot_kernel() {
    int b = blockIdx.x;
    __shared__ float sh[256];
    float s = 0.f;
    for (int i = threadIdx.x; i < DD; i += 256) s += g_rowsum[b * DD + i];
    sh[threadIdx.x] = s;
    __syncthreads();
    #pragma unroll
    for (int o = 128; o > 0; o >>= 1) {
        if (threadIdx.x < o) sh[threadIdx.x] += sh[threadIdx.x + o];
        __syncthreads();
    }
    if (threadIdx.x == 0) g_tot[b] = sh[0];
}

// ---------------------------------------------------------------------------
// Kernel 5: double centering + upper-triangular gather
// out[b, i*D - i(i-1)/2 + (j-i)] = dcov[b,i,j] - s_i/D - s_j/D + tot/D^2
// ---------------------------------------------------------------------------
__global__ void out_kernel(float* __restrict__ out) {
    int i = blockIdx.x;
    int b = blockIdx.y;
    const float inv_d = 1.f / DD;
    float si  = g_rowsum[b * DD + i] * inv_d;
    float tot = g_tot[b] * (inv_d * inv_d);
    const float* dcr = g_dcov + ((size_t)b * DD + i) * DD;
    size_t base = (size_t)b * TRI + (size_t)i * DD - ((size_t)i * (i - 1)) / 2 - i;
    for (int j = i + threadIdx.x; j < DD; j += blockDim.x) {
        float sj = g_rowsum[b * DD + j] * inv_d;
        out[base + j] = dcr[j] - si - sj + tot;
    }
}

// ---------------------------------------------------------------------------
extern "C" void kernel_launch(void* const* d_in, const int* in_sizes, int n_in,
                              void* d_out, int out_size) {
    const float* x = (const float*)d_in[0];
    float* out = (float*)d_out;

    diag_kernel<<<(BB * DD) / 8, 256>>>(x);                 // 20480 warps
    gram_kernel<<<dim3(NT * (NT + 1) / 2, BB), 256>>>(x);   // 55 x 32 blocks
    rowsum_kernel<<<(BB * DD) / 8, 256>>>();
    tot_kernel<<<BB, 256>>>();
    out_kernel<<<dim3(DD, BB), 256>>>(out);
}

// round 6
// speedup vs baseline: 2.5855x; 2.5855x over previous
#include <cuda_runtime.h>
#include <cuda_bf16.h>
#include <cstdint>

#define BB 32
#define DD 640
#define MM 1024
#define TRI (DD*(DD+1)/2)
#define TEMPR (1.0f/(2.0f*DD*MM))
#define EPSV 1e-5f

#define NBL 5                 /* 640/128 tile blocks per dim */
#define NTILE (NBL*(NBL+1)/2) /* 15 upper-tri tiles */
#define KC 64                 /* bf16 K per chunk = 128 bytes/row */
#define NCH (MM/KC)           /* 16 chunks */

// ---- device scratch (no runtime allocation) ----
__device__ __align__(256) __nv_bfloat16 g_hi[(size_t)BB*DD*MM];
__device__ __align__(256) __nv_bfloat16 g_lo[(size_t)BB*DD*MM];
__device__ __align__(256) float g_dcov[(size_t)BB*DD*DD];   // upper tiles only
__device__ float g_diag[BB*DD];
__device__ float g_rspart[(size_t)BB*NBL*DD];
__device__ float g_rowsum[BB*DD];
__device__ float g_tot[BB];

// ---------------- baseline-PTX helpers (no 'a'-features) ----------------
__device__ __forceinline__ uint32_t smem_u32(const void* p) {
    uint32_t a;
    asm("{ .reg .u64 t; cvta.to.shared.u64 t, %1; cvt.u32.u64 %0, t; }" : "=r"(a) : "l"(p));
    return a;
}
#define SW128(o) ((o) ^ (((o) >> 3) & 0x70))

#define CP_ASYNC16(dst, src) \
    asm volatile("cp.async.cg.shared.global [%0], [%1], 16;" :: "r"(dst), "l"(src) : "memory")
#define CP_COMMIT() asm volatile("cp.async.commit_group;" ::: "memory")
#define CP_WAIT0()  asm volatile("cp.async.wait_group 0;" ::: "memory")

#define LDSM4(r, addr) \
    asm volatile("ldmatrix.sync.aligned.m8n8.x4.shared.b16 {%0,%1,%2,%3}, [%4];" \
                 : "=r"((r)[0]), "=r"((r)[1]), "=r"((r)[2]), "=r"((r)[3]) : "r"(addr))

#define MMA_BF16(c, a, b0, b1) \
    asm volatile("mma.sync.aligned.m16n8k16.row.col.f32.bf16.bf16.f32 " \
                 "{%0,%1,%2,%3}, {%4,%5,%6,%7}, {%8,%9}, {%0,%1,%2,%3};" \
                 : "+f"((c)[0]), "+f"((c)[1]), "+f"((c)[2]), "+f"((c)[3]) \
                 : "r"((a)[0]), "r"((a)[1]), "r"((a)[2]), "r"((a)[3]), "r"(b0), "r"(b1))

// ---------------------------------------------------------------------------
// Kernel 1: fp32 -> (hi, lo) bf16 split + diag row-norms. One warp per row.
// ---------------------------------------------------------------------------
__global__ void conv_diag_kernel(const float* __restrict__ x) {
    int w = (blockIdx.x * blockDim.x + threadIdx.x) >> 5;
    int lane = threadIdx.x & 31;
    if (w >= BB * DD) return;
    const float4* row = reinterpret_cast<const float4*>(x + (size_t)w * MM);
    __nv_bfloat16* ph = g_hi + (size_t)w * MM;
    __nv_bfloat16* pl = g_lo + (size_t)w * MM;
    float s = 0.f;
    #pragma unroll
    for (int m4 = lane; m4 < MM / 4; m4 += 32) {
        float4 v = row[m4];
        s += v.x*v.x + v.y*v.y + v.z*v.z + v.w*v.w;
        __nv_bfloat16 h0 = __float2bfloat16(v.x), h1 = __float2bfloat16(v.y);
        __nv_bfloat16 h2 = __float2bfloat16(v.z), h3 = __float2bfloat16(v.w);
        __nv_bfloat16 l0 = __float2bfloat16(v.x - __bfloat162float(h0));
        __nv_bfloat16 l1 = __float2bfloat16(v.y - __bfloat162float(h1));
        __nv_bfloat16 l2 = __float2bfloat16(v.z - __bfloat162float(h2));
        __nv_bfloat16 l3 = __float2bfloat16(v.w - __bfloat162float(h3));
        uint2 hp, lp;
        hp.x = ((uint32_t)__bfloat16_as_ushort(h1) << 16) | __bfloat16_as_ushort(h0);
        hp.y = ((uint32_t)__bfloat16_as_ushort(h3) << 16) | __bfloat16_as_ushort(h2);
        lp.x = ((uint32_t)__bfloat16_as_ushort(l1) << 16) | __bfloat16_as_ushort(l0);
        lp.y = ((uint32_t)__bfloat16_as_ushort(l3) << 16) | __bfloat16_as_ushort(l2);
        *reinterpret_cast<uint2*>(ph + m4 * 4) = hp;
        *reinterpret_cast<uint2*>(pl + m4 * 4) = lp;
    }
    #pragma unroll
    for (int o = 16; o > 0; o >>= 1) s += __shfl_down_sync(0xffffffffu, s, o);
    if (lane == 0) g_diag[w] = s;
}

// ---------------------------------------------------------------------------
// Kernel 2: Gram via mma.sync bf16 (hi/lo, 3 passes), 128x128 tiles,
// double-buffered cp.async, fused dcov epilogue + row/col partial sums.
// ---------------------------------------------------------------------------
// smem: two 64KB stages, each: Ah(16K) Al(16K) Bh(16K) Bl(16K). 128KB total.
// Epilogue reuses it as float stage[128][132] (67.6KB).
#define STAGE_BYTES 65536
#define SMEM_BYTES  131072

__device__ __forceinline__ void load_tile_async(const __nv_bfloat16* src,
                                                uint32_t dst, int kc, int tid) {
    #pragma unroll
    for (int it = 0; it < 4; it++) {
        int idx = it * 256 + tid;
        int row = idx >> 3, c16 = idx & 7;
        const char* s = (const char*)src + (size_t)row * (MM * 2) + kc * (KC * 2) + c16 * 16;
        uint32_t off = (uint32_t)(row * 128 + c16 * 16);
        CP_ASYNC16(dst + SW128(off), s);
    }
}

__global__ __launch_bounds__(256, 1) void gram_mma_kernel() {
    extern __shared__ __align__(1024) uint8_t smem[];
    uint32_t sb = smem_u32(smem);
    __shared__ float s_di[128], s_dj[128];

    int tid = threadIdx.x;
    int wid = tid >> 5, lane = tid & 31;
    int bb = blockIdx.y;

    int lin = blockIdx.x, ti = 0, rem = lin;
    while (rem >= NBL - ti) { rem -= NBL - ti; ti++; }
    int tj = ti + rem;
    bool isdiag = (ti == tj);
    int gi0 = ti * 128, gj0 = tj * 128;

    const __nv_bfloat16* pAh = g_hi + ((size_t)(bb * DD + gi0)) * MM;
    const __nv_bfloat16* pAl = g_lo + ((size_t)(bb * DD + gi0)) * MM;
    const __nv_bfloat16* pBh = isdiag ? pAh : g_hi + ((size_t)(bb * DD + gj0)) * MM;
    const __nv_bfloat16* pBl = isdiag ? pAl : g_lo + ((size_t)(bb * DD + gj0)) * MM;

    int wr = wid >> 2, wc = wid & 3;          // 2 x 4 warp grid; 64x32 warp tile

    // ldmatrix source coords (within tile, bytes)
    int a_row = lane & 15;
    int a_kb  = (lane >> 4) * 16;
    int b_row = ((lane >> 4) << 3) + (lane & 7);
    int b_kb  = ((lane >> 3) & 1) * 16;

    float acc[4][4][4];
    #pragma unroll
    for (int i = 0; i < 4; i++)
        #pragma unroll
        for (int j = 0; j < 4; j++)
            #pragma unroll
            for (int k = 0; k < 4; k++) acc[i][j][k] = 0.f;

    // preload chunk 0 into stage 0
    load_tile_async(pAh, sb + 0,     0, tid);
    load_tile_async(pAl, sb + 16384, 0, tid);
    load_tile_async(pBh, sb + 32768, 0, tid);
    load_tile_async(pBl, sb + 49152, 0, tid);
    CP_COMMIT();

    for (int kc = 0; kc < NCH; kc++) {
        uint32_t cur = sb + (uint32_t)(kc & 1) * STAGE_BYTES;
        CP_WAIT0();
        __syncthreads();
        if (kc + 1 < NCH) {
            uint32_t nxt = sb + (uint32_t)((kc + 1) & 1) * STAGE_BYTES;
            load_tile_async(pAh, nxt + 0,     kc + 1, tid);
            load_tile_async(pAl, nxt + 16384, kc + 1, tid);
            load_tile_async(pBh, nxt + 32768, kc + 1, tid);
            load_tile_async(pBl, nxt + 49152, kc + 1, tid);
            CP_COMMIT();
        }
        uint32_t Ah = cur, Al = cur + 16384, Bh = cur + 32768, Bl = cur + 49152;
        #pragma unroll
        for (int ks = 0; ks < KC / 16; ks++) {
            uint32_t ah[4][4], al[4][4], bh[2][4], bl[2][4];
            #pragma unroll
            for (int mt = 0; mt < 4; mt++) {
                uint32_t off = (uint32_t)((wr * 64 + mt * 16 + a_row) * 128 + ks * 32 + a_kb);
                LDSM4(ah[mt], Ah + SW128(off));
                LDSM4(al[mt], Al + SW128(off));
            }
            #pragma unroll
            for (int n2 = 0; n2 < 2; n2++) {
                uint32_t off = (uint32_t)((wc * 32 + n2 * 16 + b_row) * 128 + ks * 32 + b_kb);
                LDSM4(bh[n2], Bh + SW128(off));
                LDSM4(bl[n2], Bl + SW128(off));
            }
            #pragma unroll
            for (int mt = 0; mt < 4; mt++) {
                #pragma unroll
                for (int nt = 0; nt < 4; nt++) {
                    int n2 = nt >> 1, hb = (nt & 1) * 2;
                    float* c = acc[mt][nt];
                    MMA_BF16(c, ah[mt], bh[n2][hb], bh[n2][hb + 1]);
                    MMA_BF16(c, ah[mt], bl[n2][hb], bl[n2][hb + 1]);
                    MMA_BF16(c, al[mt], bh[n2][hb], bh[n2][hb + 1]);
                }
            }
        }
    }

    // ---- epilogue ----
    if (tid < 128) {
        s_di[tid] = g_diag[bb * DD + gi0 + tid];
        s_dj[tid] = g_diag[bb * DD + gj0 + tid];
    }
    __syncthreads();   // also: all warps done reading mma smem buffers

    float* stage = reinterpret_cast<float*>(smem);   // [128][132]
    int qr = lane >> 2, qc = lane & 3;
    #pragma unroll
    for (int mt = 0; mt < 4; mt++) {
        int r0 = wr * 64 + mt * 16 + qr;
        float di0 = s_di[r0], di1 = s_di[r0 + 8];
        #pragma unroll
        for (int nt = 0; nt < 4; nt++) {
            int c0 = wc * 32 + nt * 8 + qc * 2;
            float dj0 = s_dj[c0], dj1 = s_dj[c0 + 1];
            float* c = acc[mt][nt];
            float v00 = sqrtf(fmaf(TEMPR, fmaxf(di0 + dj0 - 2.f * c[0], 0.f), EPSV));
            float v01 = sqrtf(fmaf(TEMPR, fmaxf(di0 + dj1 - 2.f * c[1], 0.f), EPSV));
            float v10 = sqrtf(fmaf(TEMPR, fmaxf(di1 + dj0 - 2.f * c[2], 0.f), EPSV));
            float v11 = sqrtf(fmaf(TEMPR, fmaxf(di1 + dj1 - 2.f * c[3], 0.f), EPSV));
            stage[r0 * 132 + c0]       = v00;
            stage[r0 * 132 + c0 + 1]   = v01;
            stage[(r0 + 8) * 132 + c0]     = v10;
            stage[(r0 + 8) * 132 + c0 + 1] = v11;
        }
    }
    __syncthreads();

    // coalesced dcov store (upper tile only)
    float* dcb = g_dcov + (size_t)bb * DD * DD;
    #pragma unroll
    for (int it = 0; it < 64; it++) {
        int idx = it * 256 + tid;
        int r = idx >> 7, cjj = idx & 127;
        dcb[(size_t)(gi0 + r) * DD + gj0 + cjj] = stage[r * 132 + cjj];
    }

    // row partial sums -> slot [tj][gi0+r]
    #pragma unroll
    for (int rr = 0; rr < 16; rr++) {
        int r = wid * 16 + rr;
        float s = stage[r * 132 + lane] + stage[r * 132 + lane + 32] +
                  stage[r * 132 + lane + 64] + stage[r * 132 + lane + 96];
        #pragma unroll
        for (int o = 16; o > 0; o >>= 1) s += __shfl_down_sync(0xffffffffu, s, o);
        if (lane == 0) g_rspart[((size_t)bb * NBL + tj) * DD + gi0 + r] = s;
    }
    // col partial sums (mirror) -> slot [ti][gj0+c], off-diagonal only
    if (!isdiag && tid < 128) {
        float s = 0.f;
        #pragma unroll 8
        for (int r = 0; r < 128; r++) s += stage[r * 132 + tid];
        g_rspart[((size_t)bb * NBL + ti) * DD + gj0 + tid] = s;
    }
}

// ---------------------------------------------------------------------------
// Kernel 3: combine partials -> rowsum + per-batch total (deterministic)
// ---------------------------------------------------------------------------
__global__ void combine_kernel() {
    int b = blockIdx.x;
    __shared__ float sh[256];
    float loc = 0.f;
    for (int i = threadIdx.x; i < DD; i += 256) {
        float s = 0.f;
        #pragma unroll
        for (int t = 0; t < NBL; t++) s += g_rspart[((size_t)b * NBL + t) * DD + i];
        g_rowsum[b * DD + i] = s;
        loc += s;
    }
    sh[threadIdx.x] = loc;
    __syncthreads();
    #pragma unroll
    for (int o = 128; o > 0; o >>= 1) {
        if (threadIdx.x < o) sh[threadIdx.x] += sh[threadIdx.x + o];
        __syncthreads();
    }
    if (threadIdx.x == 0) g_tot[b] = sh[0];
}

// ---------------------------------------------------------------------------
// Kernel 4: double centering + triu gather (reads upper triangle only)
// ---------------------------------------------------------------------------
__global__ void out_kernel(float* __restrict__ out) {
    int i = blockIdx.x;
    int b = blockIdx.y;
    const float inv_d = 1.f / DD;
    float si  = g_rowsum[b * DD + i] * inv_d;
    float tot = g_tot[b] * (inv_d * inv_d);
    const float* dcr = g_dcov + ((size_t)b * DD + i) * DD;
    size_t base = (size_t)b * TRI + (size_t)i * DD - ((size_t)i * (i - 1)) / 2 - i;
    for (int j = i + threadIdx.x; j < DD; j += blockDim.x) {
        float sj = g_rowsum[b * DD + j] * inv_d;
        out[base + j] = dcr[j] - si - sj + tot;
    }
}

// ---------------------------------------------------------------------------
extern "C" void kernel_launch(void* const* d_in, const int* in_sizes, int n_in,
                              void* d_out, int out_size) {
    const float* x = (const float*)d_in[0];
    float* out = (float*)d_out;

    cudaFuncSetAttribute(gram_mma_kernel,
                         cudaFuncAttributeMaxDynamicSharedMemorySize, SMEM_BYTES);

    conv_diag_kernel<<<(BB * DD) / 8, 256>>>(x);
    gram_mma_kernel<<<dim3(NTILE, BB), 256, SMEM_BYTES>>>();
    combine_kernel<<<BB, 256>>>();
    out_kernel<<<dim3(DD, BB), 256>>>(out);
}

// round 7
// speedup vs baseline: 2.8654x; 1.1082x over previous
#include <cuda_runtime.h>
#include <cuda_bf16.h>
#include <cstdint>

#define BB 32
#define DD 640
#define MM 1024
#define TRI (DD*(DD+1)/2)
#define TEMPR (1.0f/(2.0f*DD*MM))
#define EPSV 1e-5f

#define NBL 5                 /* 640/128 tile blocks per dim */
#define NTILE (NBL*(NBL+1)/2) /* 15 upper-tri tiles */
#define KC 32                 /* bf16 K per chunk; hi|lo packed -> 128B/row */
#define NCH (MM/KC)           /* 32 chunks */

// ---- device scratch (no runtime allocation) ----
// g_hl row layout: per source row, 32 chunks of [hi x32 bf16 | lo x32 bf16]
// => (row, kc) block is 128 contiguous bytes. Row stride = 2048 bf16 = 4KB.
__device__ __align__(256) __nv_bfloat16 g_hl[(size_t)BB*DD*2048];  // 83.9 MB
__device__ __align__(256) float g_dcov[(size_t)BB*DD*DD];          // upper tiles only
__device__ float g_diag[BB*DD];
__device__ float g_rspart[(size_t)BB*NBL*DD];
__device__ float g_rowsum[BB*DD];   // pre-scaled by 1/D
__device__ float g_tot[BB];         // pre-scaled by 1/D^2

// ---------------- baseline-PTX helpers ----------------
__device__ __forceinline__ uint32_t smem_u32(const void* p) {
    uint32_t a;
    asm("{ .reg .u64 t; cvta.to.shared.u64 t, %1; cvt.u32.u64 %0, t; }" : "=r"(a) : "l"(p));
    return a;
}
#define SW128(o) ((o) ^ (((o) >> 3) & 0x70))

#define CP_ASYNC16(dst, src) \
    asm volatile("cp.async.cg.shared.global [%0], [%1], 16;" :: "r"(dst), "l"(src) : "memory")
#define CP_COMMIT() asm volatile("cp.async.commit_group;" ::: "memory")
#define CP_WAIT0()  asm volatile("cp.async.wait_group 0;" ::: "memory")

#define LDSM4(r, addr) \
    asm volatile("ldmatrix.sync.aligned.m8n8.x4.shared.b16 {%0,%1,%2,%3}, [%4];" \
                 : "=r"((r)[0]), "=r"((r)[1]), "=r"((r)[2]), "=r"((r)[3]) : "r"(addr))

#define MMA_BF16(c, a, b0, b1) \
    asm volatile("mma.sync.aligned.m16n8k16.row.col.f32.bf16.bf16.f32 " \
                 "{%0,%1,%2,%3}, {%4,%5,%6,%7}, {%8,%9}, {%0,%1,%2,%3};" \
                 : "+f"((c)[0]), "+f"((c)[1]), "+f"((c)[2]), "+f"((c)[3]) \
                 : "r"((a)[0]), "r"((a)[1]), "r"((a)[2]), "r"((a)[3]), "r"(b0), "r"(b1))

// ---------------------------------------------------------------------------
// Kernel 1: fp32 -> packed (hi|lo) bf16 + diag row-norms. One warp per row.
// ---------------------------------------------------------------------------
__global__ void conv_diag_kernel(const float* __restrict__ x) {
    int w = (blockIdx.x * blockDim.x + threadIdx.x) >> 5;
    int lane = threadIdx.x & 31;
    if (w >= BB * DD) return;
    const float4* row = reinterpret_cast<const float4*>(x + (size_t)w * MM);
    __nv_bfloat16* pr = g_hl + (size_t)w * 2048;
    float s = 0.f;
    #pragma unroll
    for (int m4 = lane; m4 < MM / 4; m4 += 32) {
        float4 v = row[m4];
        s += v.x*v.x + v.y*v.y + v.z*v.z + v.w*v.w;
        __nv_bfloat16 h0 = __float2bfloat16(v.x), h1 = __float2bfloat16(v.y);
        __nv_bfloat16 h2 = __float2bfloat16(v.z), h3 = __float2bfloat16(v.w);
        __nv_bfloat16 l0 = __float2bfloat16(v.x - __bfloat162float(h0));
        __nv_bfloat16 l1 = __float2bfloat16(v.y - __bfloat162float(h1));
        __nv_bfloat16 l2 = __float2bfloat16(v.z - __bfloat162float(h2));
        __nv_bfloat16 l3 = __float2bfloat16(v.w - __bfloat162float(h3));
        uint2 hp, lp;
        hp.x = ((uint32_t)__bfloat16_as_ushort(h1) << 16) | __bfloat16_as_ushort(h0);
        hp.y = ((uint32_t)__bfloat16_as_ushort(h3) << 16) | __bfloat16_as_ushort(h2);
        lp.x = ((uint32_t)__bfloat16_as_ushort(l1) << 16) | __bfloat16_as_ushort(l0);
        lp.y = ((uint32_t)__bfloat16_as_ushort(l3) << 16) | __bfloat16_as_ushort(l2);
        int col0 = m4 * 4;
        int kc = col0 >> 5, wi = col0 & 31;
        *reinterpret_cast<uint2*>(pr + kc * 64 + wi)      = hp;
        *reinterpret_cast<uint2*>(pr + kc * 64 + 32 + wi) = lp;
    }
    #pragma unroll
    for (int o = 16; o > 0; o >>= 1) s += __shfl_down_sync(0xffffffffu, s, o);
    if (lane == 0) g_diag[w] = s;
}

// ---------------------------------------------------------------------------
// Kernel 2: Gram via mma.sync bf16 (hi/lo, 3 passes), 128x128 tiles,
// KC=32 packed hi|lo rows, double-buffered cp.async, 2 CTAs/SM.
// ---------------------------------------------------------------------------
// dyn smem: two 32KB stages (A 16K @0, B 16K @16K). Epilogue reuses as
// float stage[64][132] (33.8KB), in two 64-row halves.
#define STAGE_BYTES 32768
#define SMEM_BYTES  65536

__device__ __forceinline__ void load_tile_async(const __nv_bfloat16* src,
                                                uint32_t dst, int kc, int tid) {
    #pragma unroll
    for (int it = 0; it < 4; it++) {
        int idx = it * 256 + tid;           // 0..1023
        int row = idx >> 3, c16 = idx & 7;
        const char* s = (const char*)src + (size_t)row * 4096 + kc * 128 + c16 * 16;
        uint32_t off = (uint32_t)(row * 128 + c16 * 16);
        CP_ASYNC16(dst + SW128(off), s);
    }
}

__global__ __launch_bounds__(256, 2) void gram_mma_kernel() {
    extern __shared__ __align__(1024) uint8_t smem[];
    uint32_t sb = smem_u32(smem);
    __shared__ float s_di[128], s_dj[128];

    int tid = threadIdx.x;
    int wid = tid >> 5, lane = tid & 31;
    int bb = blockIdx.y;

    int lin = blockIdx.x, ti = 0, rem = lin;
    while (rem >= NBL - ti) { rem -= NBL - ti; ti++; }
    int tj = ti + rem;
    bool isdiag = (ti == tj);
    int gi0 = ti * 128, gj0 = tj * 128;

    const __nv_bfloat16* pA = g_hl + (size_t)(bb * DD + gi0) * 2048;
    const __nv_bfloat16* pB = g_hl + (size_t)(bb * DD + gj0) * 2048;

    int wr = wid >> 2, wc = wid & 3;   // 2 x 4 warp grid; warp tile 64x32

    int a_row = lane & 15;
    int a_kb  = (lane >> 4) * 16;
    int b_row = ((lane >> 4) << 3) + (lane & 7);
    int b_kb  = ((lane >> 3) & 1) * 16;

    float acc[4][4][4];
    #pragma unroll
    for (int i = 0; i < 4; i++)
        #pragma unroll
        for (int j = 0; j < 4; j++)
            #pragma unroll
            for (int k = 0; k < 4; k++) acc[i][j][k] = 0.f;

    // preload chunk 0
    load_tile_async(pA, sb + 0, 0, tid);
    if (!isdiag) load_tile_async(pB, sb + 16384, 0, tid);
    CP_COMMIT();

    for (int kc = 0; kc < NCH; kc++) {
        uint32_t cur = sb + (uint32_t)(kc & 1) * STAGE_BYTES;
        CP_WAIT0();
        __syncthreads();
        if (kc + 1 < NCH) {
            uint32_t nxt = sb + (uint32_t)((kc + 1) & 1) * STAGE_BYTES;
            load_tile_async(pA, nxt + 0, kc + 1, tid);
            if (!isdiag) load_tile_async(pB, nxt + 16384, kc + 1, tid);
            CP_COMMIT();
        }
        uint32_t Ab = cur;
        uint32_t Bb = isdiag ? cur : cur + 16384;
        #pragma unroll
        for (int ks = 0; ks < 2; ks++) {
            uint32_t bh[2][4], bl[2][4];
            #pragma unroll
            for (int n2 = 0; n2 < 2; n2++) {
                uint32_t off = (uint32_t)((wc * 32 + n2 * 16 + b_row) * 128 + ks * 32 + b_kb);
                LDSM4(bh[n2], Bb + SW128(off));
                LDSM4(bl[n2], Bb + SW128(off + 64));
            }
            #pragma unroll
            for (int mtg = 0; mtg < 2; mtg++) {
                uint32_t ah[2][4], al[2][4];
                #pragma unroll
                for (int m2 = 0; m2 < 2; m2++) {
                    int mt = mtg * 2 + m2;
                    uint32_t off = (uint32_t)((wr * 64 + mt * 16 + a_row) * 128 + ks * 32 + a_kb);
                    LDSM4(ah[m2], Ab + SW128(off));
                    LDSM4(al[m2], Ab + SW128(off + 64));
                }
                #pragma unroll
                for (int m2 = 0; m2 < 2; m2++) {
                    int mt = mtg * 2 + m2;
                    #pragma unroll
                    for (int nt = 0; nt < 4; nt++) {
                        int n2 = nt >> 1, hb = (nt & 1) * 2;
                        float* c = acc[mt][nt];
                        MMA_BF16(c, ah[m2], bh[n2][hb], bh[n2][hb + 1]);
                        MMA_BF16(c, ah[m2], bl[n2][hb], bl[n2][hb + 1]);
                        MMA_BF16(c, al[m2], bh[n2][hb], bh[n2][hb + 1]);
                    }
                }
            }
        }
    }

    // ---- epilogue: two 64-row halves through stage[64][132] ----
    if (tid < 128) {
        s_di[tid] = g_diag[bb * DD + gi0 + tid];
        s_dj[tid] = g_diag[bb * DD + gj0 + tid];
    }
    __syncthreads();   // all warps done with pipeline smem

    float* stage = reinterpret_cast<float*>(smem);   // [64][132]
    float* dcb = g_dcov + (size_t)bb * DD * DD;
    int qr = lane >> 2, qc = lane & 3;
    float csum = 0.f;   // column partial (tid<128)

    #pragma unroll
    for (int h = 0; h < 2; h++) {
        if (wr == h) {
            #pragma unroll
            for (int mt = 0; mt < 4; mt++) {
                int rl = mt * 16 + qr;                 // local row 0..63
                float di0 = s_di[h * 64 + rl], di1 = s_di[h * 64 + rl + 8];
                #pragma unroll
                for (int nt = 0; nt < 4; nt++) {
                    int c0 = wc * 32 + nt * 8 + qc * 2;
                    float dj0 = s_dj[c0], dj1 = s_dj[c0 + 1];
                    float* c = acc[mt][nt];
                    stage[rl * 132 + c0]         = sqrtf(fmaf(TEMPR, fmaxf(di0 + dj0 - 2.f * c[0], 0.f), EPSV));
                    stage[rl * 132 + c0 + 1]     = sqrtf(fmaf(TEMPR, fmaxf(di0 + dj1 - 2.f * c[1], 0.f), EPSV));
                    stage[(rl + 8) * 132 + c0]     = sqrtf(fmaf(TEMPR, fmaxf(di1 + dj0 - 2.f * c[2], 0.f), EPSV));
                    stage[(rl + 8) * 132 + c0 + 1] = sqrtf(fmaf(TEMPR, fmaxf(di1 + dj1 - 2.f * c[3], 0.f), EPSV));
                }
            }
        }
        __syncthreads();

        // coalesced dcov store: 64 rows x 128 cols
        #pragma unroll
        for (int it = 0; it < 32; it++) {
            int idx = it * 256 + tid;
            int r = idx >> 7, cjj = idx & 127;
            dcb[(size_t)(gi0 + h * 64 + r) * DD + gj0 + cjj] = stage[r * 132 + cjj];
        }
        // row partial sums -> slot [tj]
        #pragma unroll
        for (int rr = 0; rr < 8; rr++) {
            int rl = wid * 8 + rr;
            float s = stage[rl * 132 + lane] + stage[rl * 132 + lane + 32] +
                      stage[rl * 132 + lane + 64] + stage[rl * 132 + lane + 96];
            #pragma unroll
            for (int o = 16; o > 0; o >>= 1) s += __shfl_down_sync(0xffffffffu, s, o);
            if (lane == 0)
                g_rspart[((size_t)bb * NBL + tj) * DD + gi0 + h * 64 + rl] = s;
        }
        // column partial accumulation (mirror), off-diagonal only
        if (!isdiag && tid < 128) {
            #pragma unroll 8
            for (int r = 0; r < 64; r++) csum += stage[r * 132 + tid];
        }
        __syncthreads();
    }
    if (!isdiag && tid < 128)
        g_rspart[((size_t)bb * NBL + ti) * DD + gj0 + tid] = csum;
}

// ---------------------------------------------------------------------------
// Kernel 3: combine partials -> rowsum/D + tot/D^2 (deterministic)
// ---------------------------------------------------------------------------
__global__ void combine_kernel() {
    int b = blockIdx.x;
    __shared__ float sh[256];
    const float inv_d = 1.f / DD;
    float loc = 0.f;
    for (int i = threadIdx.x; i < DD; i += 256) {
        float s = 0.f;
        #pragma unroll
        for (int t = 0; t < NBL; t++) s += g_rspart[((size_t)b * NBL + t) * DD + i];
        g_rowsum[b * DD + i] = s * inv_d;
        loc += s;
    }
    sh[threadIdx.x] = loc;
    __syncthreads();
    #pragma unroll
    for (int o = 128; o > 0; o >>= 1) {
        if (threadIdx.x < o) sh[threadIdx.x] += sh[threadIdx.x + o];
        __syncthreads();
    }
    if (threadIdx.x == 0) g_tot[b] = sh[0] * (inv_d * inv_d);
}

// ---------------------------------------------------------------------------
// Kernel 4: centering + triu gather; rows paired (p, 639-p) for balance.
// ---------------------------------------------------------------------------
__global__ void out_kernel(float* __restrict__ out) {
    int p = blockIdx.x;     // 0..319
    int b = blockIdx.y;
    float tot = g_tot[b];
    #pragma unroll
    for (int h = 0; h < 2; h++) {
        int i = h ? (DD - 1 - p) : p;
        float si = g_rowsum[b * DD + i];
        const float* dcr = g_dcov + ((size_t)b * DD + i) * DD;
        size_t base = (size_t)b * TRI + (size_t)i * DD - ((size_t)i * (i - 1)) / 2 - i;
        for (int j = i + threadIdx.x; j < DD; j += 256)
            out[base + j] = dcr[j] - si - g_rowsum[b * DD + j] + tot;
    }
}

// ---------------------------------------------------------------------------
extern "C" void kernel_launch(void* const* d_in, const int* in_sizes, int n_in,
                              void* d_out, int out_size) {
    const float* x = (const float*)d_in[0];
    float* out = (float*)d_out;

    cudaFuncSetAttribute(gram_mma_kernel,
                         cudaFuncAttributeMaxDynamicSharedMemorySize, SMEM_BYTES);

    conv_diag_kernel<<<(BB * DD) / 8, 256>>>(x);
    gram_mma_kernel<<<dim3(NTILE, BB), 256, SMEM_BYTES>>>();
    combine_kernel<<<BB, 256>>>();
    out_kernel<<<dim3(DD / 2, BB), 256>>>(out);
}